// round 1
// baseline (speedup 1.0000x reference)
#include <cuda_runtime.h>

#define NN 65536
#define NE 524288
#define HH 256
#define H4 64

// ------------------------- scratch (device globals; no allocs) -------------
__device__ float g_h   [NN*HH];
__device__ float g_h1  [NN*HH];
__device__ float g_h2  [NN*HH];
__device__ float g_skip[NN*HH];
__device__ float g_agg [NN*HH];
__device__ float g_pre [NN*HH];
__device__ int   g_deg [NN];
__device__ float g_dinv[NN];
__device__ int   g_off [NN+1];
__device__ int   g_cur [NN];
__device__ int   g_csr [NE];
__device__ int   g_cnt [NN*3];
__device__ int   g_bsum[256];
__device__ float g_ps  [256*HH];
__device__ float g_pq  [256*HH];
__device__ float g_scale[HH];
__device__ float g_shift[HH];

// ------------------------- small kernels -----------------------------------
__global__ void k_zero() {
    int i = blockIdx.x * blockDim.x + threadIdx.x;
    if (i < NN) {
        g_deg[i] = 0; g_cur[i] = 0;
        g_cnt[3*i] = 0; g_cnt[3*i+1] = 0; g_cnt[3*i+2] = 0;
    }
}

__global__ void k_hist(const int* __restrict__ row, const int* __restrict__ col,
                       const int* __restrict__ ea) {
    int e = blockIdx.x * blockDim.x + threadIdx.x;
    if (e < NE) {
        atomicAdd(&g_deg[col[e]], 1);
        atomicAdd(&g_cnt[row[e]*3 + ea[e]], 1);
    }
}

__global__ void k_scanA() {
    __shared__ int s[256];
    int b = blockIdx.x, t = threadIdx.x;
    int i = b * 256 + t;
    int v = g_deg[i];
    s[t] = v;
    __syncthreads();
    for (int d = 1; d < 256; d <<= 1) {
        int x = (t >= d) ? s[t-d] : 0;
        __syncthreads();
        s[t] += x;
        __syncthreads();
    }
    g_off[i] = s[t] - v;          // exclusive within block
    if (t == 255) g_bsum[b] = s[255];
}

__global__ void k_scanB() {
    __shared__ int s[256];
    int t = threadIdx.x;
    int v = g_bsum[t];
    s[t] = v;
    __syncthreads();
    for (int d = 1; d < 256; d <<= 1) {
        int x = (t >= d) ? s[t-d] : 0;
        __syncthreads();
        s[t] += x;
        __syncthreads();
    }
    g_bsum[t] = s[t] - v;         // exclusive
}

__global__ void k_scanC() {
    int i = blockIdx.x * blockDim.x + threadIdx.x;
    if (i < NN) {
        g_off[i] += g_bsum[i >> 8];
        g_dinv[i] = 1.0f / (float)max(g_deg[i], 1);
        if (i == NN - 1) g_off[NN] = NE;
    }
}

__global__ void k_scatter(const int* __restrict__ row, const int* __restrict__ col) {
    int e = blockIdx.x * blockDim.x + threadIdx.x;
    if (e < NE) {
        int d = col[e];
        int p = g_off[d] + atomicAdd(&g_cur[d], 1);
        g_csr[p] = row[e];
    }
}

// h[i] = emb_node[x[i]] + sum_a cnt[i][a] * emb_edge[a]
__global__ void k_inith(const int* __restrict__ x, const float* __restrict__ en,
                        const float* __restrict__ ee) {
    int i = blockIdx.x;
    int t = threadIdx.x;  // 0..63 float4 lane
    int xi = x[i];
    float c0 = (float)g_cnt[3*i], c1 = (float)g_cnt[3*i+1], c2 = (float)g_cnt[3*i+2];
    const float4* en4 = (const float4*)en;
    const float4* ee4 = (const float4*)ee;
    float4 v  = en4[xi * H4 + t];
    float4 e0 = ee4[t], e1 = ee4[H4 + t], e2 = ee4[2*H4 + t];
    v.x += c0*e0.x + c1*e1.x + c2*e2.x;
    v.y += c0*e0.y + c1*e1.y + c2*e2.y;
    v.z += c0*e0.z + c1*e1.z + c2*e2.z;
    v.w += c0*e0.w + c1*e1.w + c2*e2.w;
    ((float4*)g_h)[i * H4 + t] = v;
}

// mean-aggregate: out[i] = deg_inv[i] * sum_{e: col=i} in[csr_src[e]]
__global__ void k_agg(const float* __restrict__ in, float* __restrict__ out) {
    int w = threadIdx.x >> 5, lane = threadIdx.x & 31;
    int i = blockIdx.x * 8 + w;
    int s = g_off[i], e = g_off[i+1];
    const float4* in4 = (const float4*)in;
    float4 x0 = make_float4(0.f,0.f,0.f,0.f);
    float4 x1 = make_float4(0.f,0.f,0.f,0.f);
    for (int p = s; p < e; ++p) {
        int src = g_csr[p];
        float4 v0 = in4[src * H4 + lane];
        float4 v1 = in4[src * H4 + 32 + lane];
        x0.x += v0.x; x0.y += v0.y; x0.z += v0.z; x0.w += v0.w;
        x1.x += v1.x; x1.y += v1.y; x1.z += v1.z; x1.w += v1.w;
    }
    float di = g_dinv[i];
    x0.x *= di; x0.y *= di; x0.z *= di; x0.w *= di;
    x1.x *= di; x1.y *= di; x1.z *= di; x1.w *= di;
    ((float4*)out)[i * H4 + lane]      = x0;
    ((float4*)out)[i * H4 + 32 + lane] = x1;
}

// ------------------------- fused dual GEMM ---------------------------------
// C = A1 @ W1^T [+ A2 @ W2^T] [+ bias] [+ add1] [+ add2]
// A: [NN, 256] row-major, W: [256, 256] row-major (both K-contiguous: NT GEMM)
__global__ __launch_bounds__(256, 2)
void k_gemm(const float* __restrict__ A1, const float* __restrict__ W1,
            const float* __restrict__ A2, const float* __restrict__ W2,
            const float* __restrict__ bias,
            const float* __restrict__ add1, const float* __restrict__ add2,
            float* __restrict__ C, int dual)
{
    __shared__ float As[16][132];
    __shared__ float Ws[16][132];
    const int t  = threadIdx.x;
    const int tx = t & 15, ty = t >> 4;
    const int bm = blockIdx.x * 128;
    const int bn = blockIdx.y * 128;
    const int lr = t & 127;          // tile row loaded by this thread
    const int lk = (t >> 7) * 8;     // k-segment (0 or 8)

    float acc[8][8];
#pragma unroll
    for (int i = 0; i < 8; i++)
#pragma unroll
        for (int j = 0; j < 8; j++) acc[i][j] = 0.f;

    const int KT = dual ? 2*HH : HH;

    // prefetch first tiles
    float4 a0v = *(const float4*)&A1[(bm + lr)*HH + lk];
    float4 a1v = *(const float4*)&A1[(bm + lr)*HH + lk + 4];
    float4 w0v = *(const float4*)&W1[(bn + lr)*HH + lk];
    float4 w1v = *(const float4*)&W1[(bn + lr)*HH + lk + 4];

    for (int ks = 0; ks < KT; ks += 16) {
        __syncthreads();
        As[lk+0][lr]=a0v.x; As[lk+1][lr]=a0v.y; As[lk+2][lr]=a0v.z; As[lk+3][lr]=a0v.w;
        As[lk+4][lr]=a1v.x; As[lk+5][lr]=a1v.y; As[lk+6][lr]=a1v.z; As[lk+7][lr]=a1v.w;
        Ws[lk+0][lr]=w0v.x; Ws[lk+1][lr]=w0v.y; Ws[lk+2][lr]=w0v.z; Ws[lk+3][lr]=w0v.w;
        Ws[lk+4][lr]=w1v.x; Ws[lk+5][lr]=w1v.y; Ws[lk+6][lr]=w1v.z; Ws[lk+7][lr]=w1v.w;
        __syncthreads();

        int kn = ks + 16;
        if (kn < KT) {
            const float* An = (kn < HH) ? A1 : A2;
            const float* Wn = (kn < HH) ? W1 : W2;
            int ko = (kn & (HH-1)) + lk;
            a0v = *(const float4*)&An[(bm + lr)*HH + ko];
            a1v = *(const float4*)&An[(bm + lr)*HH + ko + 4];
            w0v = *(const float4*)&Wn[(bn + lr)*HH + ko];
            w1v = *(const float4*)&Wn[(bn + lr)*HH + ko + 4];
        }

#pragma unroll
        for (int k = 0; k < 16; k++) {
            float a[8], w[8];
            *(float4*)&a[0] = *(const float4*)&As[k][ty*8];
            *(float4*)&a[4] = *(const float4*)&As[k][ty*8 + 4];
            *(float4*)&w[0] = *(const float4*)&Ws[k][tx*8];
            *(float4*)&w[4] = *(const float4*)&Ws[k][tx*8 + 4];
#pragma unroll
            for (int i = 0; i < 8; i++)
#pragma unroll
                for (int j = 0; j < 8; j++)
                    acc[i][j] = fmaf(a[i], w[j], acc[i][j]);
        }
    }

    // epilogue
    float bv[8] = {0,0,0,0,0,0,0,0};
    if (bias) {
        *(float4*)&bv[0] = *(const float4*)&bias[bn + tx*8];
        *(float4*)&bv[4] = *(const float4*)&bias[bn + tx*8 + 4];
    }
#pragma unroll
    for (int i = 0; i < 8; i++) {
        int r = bm + ty*8 + i;
        long base = (long)r * HH + bn + tx*8;
        float v[8];
#pragma unroll
        for (int j = 0; j < 8; j++) v[j] = acc[i][j] + bv[j];
        if (add1) {
            float4 s0 = *(const float4*)&add1[base];
            float4 s1 = *(const float4*)&add1[base + 4];
            v[0]+=s0.x; v[1]+=s0.y; v[2]+=s0.z; v[3]+=s0.w;
            v[4]+=s1.x; v[5]+=s1.y; v[6]+=s1.z; v[7]+=s1.w;
        }
        if (add2) {
            float4 s0 = *(const float4*)&add2[base];
            float4 s1 = *(const float4*)&add2[base + 4];
            v[0]+=s0.x; v[1]+=s0.y; v[2]+=s0.z; v[3]+=s0.w;
            v[4]+=s1.x; v[5]+=s1.y; v[6]+=s1.z; v[7]+=s1.w;
        }
        *(float4*)&C[base]     = make_float4(v[0], v[1], v[2], v[3]);
        *(float4*)&C[base + 4] = make_float4(v[4], v[5], v[6], v[7]);
    }
}

// ------------------------- BatchNorm ----------------------------------------
__global__ void k_bnstats() {     // partial column sums over 256-row slabs of g_pre
    int b = blockIdx.x, t = threadIdx.x;
    const float* p = g_pre + (long)b * 256 * HH + t;
    float s = 0.f, q = 0.f;
    for (int r = 0; r < 256; r++) {
        float v = p[(long)r * HH];
        s += v; q += v * v;
    }
    g_ps[b*HH + t] = s;
    g_pq[b*HH + t] = q;
}

__global__ void k_bnfinal(const float* __restrict__ g, const float* __restrict__ bb) {
    int t = threadIdx.x;
    float s = 0.f, q = 0.f;
    for (int b = 0; b < 256; b++) { s += g_ps[b*HH + t]; q += g_pq[b*HH + t]; }
    float m   = s * (1.0f / NN);
    float var = q * (1.0f / NN) - m * m;
    float sc  = g[t] * rsqrtf(var + 1e-5f);
    g_scale[t] = sc;
    g_shift[t] = bb[t] - m * sc;
}

// out = prelu(g_pre * scale + shift, a)
__global__ void k_bnact(const float* __restrict__ a, float* __restrict__ out) {
    int i = blockIdx.x * blockDim.x + threadIdx.x;   // float4 index
    float al = __ldg(a);
    float4 v = ((const float4*)g_pre)[i];
    int c4 = i & (H4 - 1);
    float4 sc = ((const float4*)g_scale)[c4];
    float4 sh = ((const float4*)g_shift)[c4];
    v.x = v.x * sc.x + sh.x;  v.x = (v.x >= 0.f) ? v.x : al * v.x;
    v.y = v.y * sc.y + sh.y;  v.y = (v.y >= 0.f) ? v.y : al * v.y;
    v.z = v.z * sc.z + sh.z;  v.z = (v.z >= 0.f) ? v.z : al * v.z;
    v.w = v.w * sc.w + sh.w;  v.w = (v.w >= 0.f) ? v.w : al * v.w;
    ((float4*)out)[i] = v;
}

// ------------------------- host orchestration -------------------------------
template <typename T>
static float* symaddr(T& sym) {
    void* p = nullptr;
    cudaGetSymbolAddress(&p, sym);
    return (float*)p;
}

extern "C" void kernel_launch(void* const* d_in, const int* in_sizes, int n_in,
                              void* d_out, int out_size)
{
    const int*   x   = (const int*)d_in[0];
    const int*   row = (const int*)d_in[1];
    const int*   col = row + NE;
    const int*   ea  = (const int*)d_in[2];
    const float* en  = (const float*)d_in[3];
    const float* ee  = (const float*)d_in[4];
    const float* Wl0 = (const float*)d_in[5];
    const float* bl0 = (const float*)d_in[6];
    const float* Wr0 = (const float*)d_in[7];
    const float* Wl1 = (const float*)d_in[8];
    const float* bl1 = (const float*)d_in[9];
    const float* Wr1 = (const float*)d_in[10];
    const float* Wl2 = (const float*)d_in[11];
    const float* bl2 = (const float*)d_in[12];
    const float* Wr2 = (const float*)d_in[13];
    const float* Wsk0= (const float*)d_in[14];
    const float* Wsk1= (const float*)d_in[15];
    const float* g0  = (const float*)d_in[16];
    const float* b0  = (const float*)d_in[17];
    const float* g1  = (const float*)d_in[18];
    const float* b1  = (const float*)d_in[19];
    const float* g2  = (const float*)d_in[20];
    const float* b2  = (const float*)d_in[21];
    const float* a0  = (const float*)d_in[22];
    const float* a1  = (const float*)d_in[23];
    const float* a2  = (const float*)d_in[24];

    float* h    = symaddr(g_h);
    float* h1   = symaddr(g_h1);
    float* h2   = symaddr(g_h2);
    float* skp  = symaddr(g_skip);
    float* agg  = symaddr(g_agg);
    float* out  = (float*)d_out;

    dim3 ggrid(NN/128, HH/128);   // (512, 2)

    // --- graph preprocessing (CSR by destination, edge-attr counts) ---
    k_zero   <<<NN/256, 256>>>();
    k_hist   <<<NE/256, 256>>>(row, col, ea);
    k_scanA  <<<256, 256>>>();
    k_scanB  <<<1, 256>>>();
    k_scanC  <<<NN/256, 256>>>();
    k_scatter<<<NE/256, 256>>>(row, col);
    k_inith  <<<NN, 64>>>(x, en, ee);

    // --- layer 0 ---
    k_agg    <<<NN/8, 256>>>(h, agg);
    k_gemm   <<<ggrid, 256>>>(agg, Wl0, h, Wr0, bl0, nullptr, nullptr, symaddr(g_pre), 1);
    k_bnstats<<<256, 256>>>();
    k_bnfinal<<<1, 256>>>(g0, b0);
    k_bnact  <<<NN*H4/256, 256>>>(a0, h1);

    // --- layer 1 ---
    k_gemm   <<<ggrid, 256>>>(h, Wsk0, nullptr, nullptr, nullptr, h1, nullptr, skp, 0);
    k_agg    <<<NN/8, 256>>>(skp, agg);
    k_gemm   <<<ggrid, 256>>>(agg, Wl1, skp, Wr1, bl1, nullptr, nullptr, symaddr(g_pre), 1);
    k_bnstats<<<256, 256>>>();
    k_bnfinal<<<1, 256>>>(g1, b1);
    k_bnact  <<<NN*H4/256, 256>>>(a1, h2);

    // --- layer 2 ---
    k_gemm   <<<ggrid, 256>>>(h, Wsk1, nullptr, nullptr, nullptr, h1, h2, skp, 0);
    k_agg    <<<NN/8, 256>>>(skp, agg);
    k_gemm   <<<ggrid, 256>>>(agg, Wl2, skp, Wr2, bl2, nullptr, nullptr, symaddr(g_pre), 1);
    k_bnstats<<<256, 256>>>();
    k_bnfinal<<<1, 256>>>(g2, b2);
    k_bnact  <<<NN*H4/256, 256>>>(a2, out);
}

// round 3
// speedup vs baseline: 2.0586x; 2.0586x over previous
#include <cuda_runtime.h>
#include <cuda_bf16.h>
#include <cstdint>

#define NN 65536
#define NE 524288
#define HH 256
#define H4 64

// ------------------------- scratch (device globals; no allocs) -------------
__device__ float g_h   [NN*HH];
__device__ float g_h1  [NN*HH];
__device__ float g_h2  [NN*HH];
__device__ float g_skip[NN*HH];
__device__ float g_agg [NN*HH];
__device__ float g_pre [NN*HH];
__device__ int   g_deg [NN];
__device__ float g_dinv[NN];
__device__ int   g_off [NN+1];
__device__ int   g_cur [NN];
__device__ int   g_csr [NE];
__device__ int   g_cnt [NN*3];
__device__ int   g_bsum[256];
__device__ float g_ps  [256*HH];
__device__ float g_pq  [256*HH];
__device__ float g_scale[HH];
__device__ float g_shift[HH];

// ------------------------- small kernels -----------------------------------
__global__ void k_zero() {
    int i = blockIdx.x * blockDim.x + threadIdx.x;
    if (i < NN) {
        g_deg[i] = 0; g_cur[i] = 0;
        g_cnt[3*i] = 0; g_cnt[3*i+1] = 0; g_cnt[3*i+2] = 0;
    }
}

__global__ void k_hist(const int* __restrict__ row, const int* __restrict__ col,
                       const int* __restrict__ ea) {
    int e = blockIdx.x * blockDim.x + threadIdx.x;
    if (e < NE) {
        atomicAdd(&g_deg[col[e]], 1);
        atomicAdd(&g_cnt[row[e]*3 + ea[e]], 1);
    }
}

__global__ void k_scanA() {
    __shared__ int s[256];
    int b = blockIdx.x, t = threadIdx.x;
    int i = b * 256 + t;
    int v = g_deg[i];
    s[t] = v;
    __syncthreads();
    for (int d = 1; d < 256; d <<= 1) {
        int x = (t >= d) ? s[t-d] : 0;
        __syncthreads();
        s[t] += x;
        __syncthreads();
    }
    g_off[i] = s[t] - v;
    if (t == 255) g_bsum[b] = s[255];
}

__global__ void k_scanB() {
    __shared__ int s[256];
    int t = threadIdx.x;
    int v = g_bsum[t];
    s[t] = v;
    __syncthreads();
    for (int d = 1; d < 256; d <<= 1) {
        int x = (t >= d) ? s[t-d] : 0;
        __syncthreads();
        s[t] += x;
        __syncthreads();
    }
    g_bsum[t] = s[t] - v;
}

__global__ void k_scanC() {
    int i = blockIdx.x * blockDim.x + threadIdx.x;
    if (i < NN) {
        g_off[i] += g_bsum[i >> 8];
        g_dinv[i] = 1.0f / (float)max(g_deg[i], 1);
        if (i == NN - 1) g_off[NN] = NE;
    }
}

__global__ void k_scatter(const int* __restrict__ row, const int* __restrict__ col) {
    int e = blockIdx.x * blockDim.x + threadIdx.x;
    if (e < NE) {
        int d = col[e];
        int p = g_off[d] + atomicAdd(&g_cur[d], 1);
        g_csr[p] = row[e];
    }
}

__global__ void k_inith(const int* __restrict__ x, const float* __restrict__ en,
                        const float* __restrict__ ee) {
    int i = blockIdx.x;
    int t = threadIdx.x;
    int xi = x[i];
    float c0 = (float)g_cnt[3*i], c1 = (float)g_cnt[3*i+1], c2 = (float)g_cnt[3*i+2];
    const float4* en4 = (const float4*)en;
    const float4* ee4 = (const float4*)ee;
    float4 v  = en4[xi * H4 + t];
    float4 e0 = ee4[t], e1 = ee4[H4 + t], e2 = ee4[2*H4 + t];
    v.x += c0*e0.x + c1*e1.x + c2*e2.x;
    v.y += c0*e0.y + c1*e1.y + c2*e2.y;
    v.z += c0*e0.z + c1*e1.z + c2*e2.z;
    v.w += c0*e0.w + c1*e1.w + c2*e2.w;
    ((float4*)g_h)[i * H4 + t] = v;
}

__global__ void k_agg(const float* __restrict__ in, float* __restrict__ out) {
    int w = threadIdx.x >> 5, lane = threadIdx.x & 31;
    int i = blockIdx.x * 8 + w;
    int s = g_off[i], e = g_off[i+1];
    const float4* in4 = (const float4*)in;
    float4 x0 = make_float4(0.f,0.f,0.f,0.f);
    float4 x1 = make_float4(0.f,0.f,0.f,0.f);
    for (int p = s; p < e; ++p) {
        int src = g_csr[p];
        float4 v0 = in4[src * H4 + lane];
        float4 v1 = in4[src * H4 + 32 + lane];
        x0.x += v0.x; x0.y += v0.y; x0.z += v0.z; x0.w += v0.w;
        x1.x += v1.x; x1.y += v1.y; x1.z += v1.z; x1.w += v1.w;
    }
    float di = g_dinv[i];
    x0.x *= di; x0.y *= di; x0.z *= di; x0.w *= di;
    x1.x *= di; x1.y *= di; x1.z *= di; x1.w *= di;
    ((float4*)out)[i * H4 + lane]      = x0;
    ((float4*)out)[i * H4 + 32 + lane] = x1;
}

// ------------------------- bf16-split tensor-core GEMM ----------------------
// C[128x128 tile] = A1 @ W1^T [+ A2 @ W2^T] [+ bias] [+ add1] [+ add2]
// fp32 emulated: Ah*Bh + Ah*Bl + Al*Bh, fp32 accumulate in mma.sync.

#define KS 32            // K floats per stage
#define PITCH 80         // bytes per smem row (32 bf16 = 64B + 16B pad)
#define AH_OFF 0
#define AL_OFF 10240
#define BH_OFF 20480
#define BL_OFF 30720
#define STG 40960
#define SM_BYTES (2*STG)
#define CPITCH 132       // C staging pitch in floats

#define LDM4(r, addr) \
    asm volatile("ldmatrix.sync.aligned.m8n8.x4.shared.b16 {%0,%1,%2,%3}, [%4];" \
        : "=r"((r)[0]), "=r"((r)[1]), "=r"((r)[2]), "=r"((r)[3]) : "r"(addr))

#define MMA(c, a, b0, b1) \
    asm volatile("mma.sync.aligned.m16n8k16.row.col.f32.bf16.bf16.f32 " \
        "{%0,%1,%2,%3}, {%4,%5,%6,%7}, {%8,%9}, {%0,%1,%2,%3};" \
        : "+f"((c)[0]), "+f"((c)[1]), "+f"((c)[2]), "+f"((c)[3]) \
        : "r"((a)[0]), "r"((a)[1]), "r"((a)[2]), "r"((a)[3]), "r"(b0), "r"(b1))

__device__ __forceinline__ uint32_t smem_u32(const void* p) {
    uint32_t a;
    asm("{ .reg .u64 t; cvta.to.shared.u64 t, %1; cvt.u32.u64 %0, t; }" : "=r"(a) : "l"(p));
    return a;
}

__device__ __forceinline__ void split4(float4 v, uint2& hi, uint2& lo) {
    __nv_bfloat16 hx = __float2bfloat16_rn(v.x);
    __nv_bfloat16 hy = __float2bfloat16_rn(v.y);
    __nv_bfloat16 hz = __float2bfloat16_rn(v.z);
    __nv_bfloat16 hw = __float2bfloat16_rn(v.w);
    float rx = v.x - __bfloat162float(hx);
    float ry = v.y - __bfloat162float(hy);
    float rz = v.z - __bfloat162float(hz);
    float rw = v.w - __bfloat162float(hw);
    __nv_bfloat16 lx = __float2bfloat16_rn(rx);
    __nv_bfloat16 ly = __float2bfloat16_rn(ry);
    __nv_bfloat16 lz = __float2bfloat16_rn(rz);
    __nv_bfloat16 lw = __float2bfloat16_rn(rw);
    hi.x = (uint32_t)__bfloat16_as_ushort(hx) | ((uint32_t)__bfloat16_as_ushort(hy) << 16);
    hi.y = (uint32_t)__bfloat16_as_ushort(hz) | ((uint32_t)__bfloat16_as_ushort(hw) << 16);
    lo.x = (uint32_t)__bfloat16_as_ushort(lx) | ((uint32_t)__bfloat16_as_ushort(ly) << 16);
    lo.y = (uint32_t)__bfloat16_as_ushort(lz) | ((uint32_t)__bfloat16_as_ushort(lw) << 16);
}

__global__ __launch_bounds__(256, 1)
void k_mma(const float* __restrict__ A1, const float* __restrict__ W1,
           const float* __restrict__ A2, const float* __restrict__ W2,
           const float* __restrict__ bias,
           const float* __restrict__ add1, const float* __restrict__ add2,
           float* __restrict__ C, int dual)
{
    extern __shared__ char sb[];
    const uint32_t sa = smem_u32(sb);

    const int t    = threadIdx.x;
    const int wid  = t >> 5;
    const int lane = t & 31;
    const int wm   = wid & 1;        // 2 warps in M (64 rows each)
    const int wn   = wid >> 1;       // 4 warps in N (32 cols each)
    const int bm   = blockIdx.x * 128;
    const int bn   = blockIdx.y * 128;
    const int S    = dual ? 16 : 8;

    // per-thread global-load coords: idx = it*256+t -> row idx>>3, c4 idx&7
    const int lrow = t >> 3;          // base row step 32 per it? (it*256+t)>>3 = it*32 + (t>>3)
    const int lc4  = t & 7;

    // ldmatrix base offsets (bytes, within a buffer half)
    const uint32_t a_off = (uint32_t)(wm*64 + (lane & 15)) * PITCH + ((lane >> 4) & 1) * 16;
    const uint32_t b_off = (uint32_t)(wn*32 + (lane & 7) + ((lane >> 4) & 1) * 8) * PITCH
                         + ((lane >> 3) & 1) * 16;

    float acc[4][4][4];
#pragma unroll
    for (int i = 0; i < 4; i++)
#pragma unroll
        for (int j = 0; j < 4; j++)
#pragma unroll
            for (int q = 0; q < 4; q++) acc[i][j][q] = 0.f;

    float4 ra[4], rb[4];
    // prefetch stage 0
    {
        const float* Asrc = A1; const float* Wsrc = W1;
#pragma unroll
        for (int it = 0; it < 4; it++) {
            int r = it*32 + lrow;
            ra[it] = *(const float4*)(Asrc + (size_t)(bm + r) * HH + lc4 * 4);
            rb[it] = *(const float4*)(Wsrc + (size_t)(bn + r) * HH + lc4 * 4);
        }
    }

    for (int s = 0; s < S; s++) {
        char* buf = sb + (s & 1) * STG;
        const uint32_t bufa = sa + (s & 1) * STG;

        // store current stage (convert fp32 -> bf16 hi/lo)
#pragma unroll
        for (int it = 0; it < 4; it++) {
            int r = it*32 + lrow;
            uint32_t so = (uint32_t)r * PITCH + lc4 * 8;
            uint2 hi, lo;
            split4(ra[it], hi, lo);
            *(uint2*)(buf + AH_OFF + so) = hi;
            *(uint2*)(buf + AL_OFF + so) = lo;
            split4(rb[it], hi, lo);
            *(uint2*)(buf + BH_OFF + so) = hi;
            *(uint2*)(buf + BL_OFF + so) = lo;
        }
        __syncthreads();

        // prefetch next stage
        if (s + 1 < S) {
            const float* Asrc = (s + 1 < 8) ? A1 : A2;
            const float* Wsrc = (s + 1 < 8) ? W1 : W2;
            const int ko = ((s + 1) & 7) * KS;
#pragma unroll
            for (int it = 0; it < 4; it++) {
                int r = it*32 + lrow;
                ra[it] = *(const float4*)(Asrc + (size_t)(bm + r) * HH + ko + lc4 * 4);
                rb[it] = *(const float4*)(Wsrc + (size_t)(bn + r) * HH + ko + lc4 * 4);
            }
        }

        // compute this stage: 2 x k16
#pragma unroll
        for (int kk = 0; kk < 2; kk++) {
            uint32_t ah[4][4], al[4][4], bh[2][4], bl[2][4];
#pragma unroll
            for (int mi = 0; mi < 4; mi++) {
                uint32_t ad = bufa + a_off + mi * (16 * PITCH) + kk * 32;
                LDM4(ah[mi], ad + AH_OFF);
                LDM4(al[mi], ad + AL_OFF);
            }
#pragma unroll
            for (int nb = 0; nb < 2; nb++) {
                uint32_t bd = bufa + b_off + nb * (16 * PITCH) + kk * 32;
                LDM4(bh[nb], bd + BH_OFF);
                LDM4(bl[nb], bd + BL_OFF);
            }
#pragma unroll
            for (int mi = 0; mi < 4; mi++) {
#pragma unroll
                for (int nj = 0; nj < 4; nj++) {
                    uint32_t bh0 = bh[nj >> 1][(nj & 1) * 2], bh1 = bh[nj >> 1][(nj & 1) * 2 + 1];
                    uint32_t bl0 = bl[nj >> 1][(nj & 1) * 2], bl1 = bl[nj >> 1][(nj & 1) * 2 + 1];
                    MMA(acc[mi][nj], ah[mi], bh0, bh1);
                    MMA(acc[mi][nj], ah[mi], bl0, bl1);
                    MMA(acc[mi][nj], al[mi], bh0, bh1);
                }
            }
        }
        __syncthreads();
    }

    // ---- epilogue: stage C in smem, then coalesced global write ----
    float* cst = (float*)sb;
    const int g = lane >> 2, tig = lane & 3;
#pragma unroll
    for (int mi = 0; mi < 4; mi++) {
#pragma unroll
        for (int nj = 0; nj < 4; nj++) {
            int rr = wm*64 + mi*16 + g;
            int cc = wn*32 + nj*8 + tig*2;
            *(float2*)&cst[rr * CPITCH + cc]       = make_float2(acc[mi][nj][0], acc[mi][nj][1]);
            *(float2*)&cst[(rr + 8) * CPITCH + cc] = make_float2(acc[mi][nj][2], acc[mi][nj][3]);
        }
    }
    __syncthreads();

#pragma unroll
    for (int it = 0; it < 16; it++) {
        int idx = it * 256 + t;
        int r = idx >> 5, c4 = idx & 31;
        float4 v = *(const float4*)&cst[r * CPITCH + c4 * 4];
        size_t base = (size_t)(bm + r) * HH + bn + c4 * 4;
        if (bias) {
            float4 bv = *(const float4*)&bias[bn + c4 * 4];
            v.x += bv.x; v.y += bv.y; v.z += bv.z; v.w += bv.w;
        }
        if (add1) {
            float4 s1 = *(const float4*)&add1[base];
            v.x += s1.x; v.y += s1.y; v.z += s1.z; v.w += s1.w;
        }
        if (add2) {
            float4 s2 = *(const float4*)&add2[base];
            v.x += s2.x; v.y += s2.y; v.z += s2.z; v.w += s2.w;
        }
        *(float4*)&C[base] = v;
    }
}

// ------------------------- BatchNorm ----------------------------------------
__global__ void k_bnstats() {
    int b = blockIdx.x, t = threadIdx.x;
    const float* p = g_pre + (long)b * 256 * HH + t;
    float s = 0.f, q = 0.f;
    for (int r = 0; r < 256; r++) {
        float v = p[(long)r * HH];
        s += v; q += v * v;
    }
    g_ps[b*HH + t] = s;
    g_pq[b*HH + t] = q;
}

__global__ void k_bnfinal(const float* __restrict__ g, const float* __restrict__ bb) {
    int t = threadIdx.x;
    float s = 0.f, q = 0.f;
    for (int b = 0; b < 256; b++) { s += g_ps[b*HH + t]; q += g_pq[b*HH + t]; }
    float m   = s * (1.0f / NN);
    float var = q * (1.0f / NN) - m * m;
    float sc  = g[t] * rsqrtf(var + 1e-5f);
    g_scale[t] = sc;
    g_shift[t] = bb[t] - m * sc;
}

__global__ void k_bnact(const float* __restrict__ a, float* __restrict__ out) {
    int i = blockIdx.x * blockDim.x + threadIdx.x;
    float al = __ldg(a);
    float4 v = ((const float4*)g_pre)[i];
    int c4 = i & (H4 - 1);
    float4 sc = ((const float4*)g_scale)[c4];
    float4 sh = ((const float4*)g_shift)[c4];
    v.x = v.x * sc.x + sh.x;  v.x = (v.x >= 0.f) ? v.x : al * v.x;
    v.y = v.y * sc.y + sh.y;  v.y = (v.y >= 0.f) ? v.y : al * v.y;
    v.z = v.z * sc.z + sh.z;  v.z = (v.z >= 0.f) ? v.z : al * v.z;
    v.w = v.w * sc.w + sh.w;  v.w = (v.w >= 0.f) ? v.w : al * v.w;
    ((float4*)out)[i] = v;
}

// ------------------------- host orchestration -------------------------------
template <typename T>
static float* symaddr(T& sym) {
    void* p = nullptr;
    cudaGetSymbolAddress(&p, sym);
    return (float*)p;
}

extern "C" void kernel_launch(void* const* d_in, const int* in_sizes, int n_in,
                              void* d_out, int out_size)
{
    const int*   x   = (const int*)d_in[0];
    const int*   row = (const int*)d_in[1];
    const int*   col = row + NE;
    const int*   ea  = (const int*)d_in[2];
    const float* en  = (const float*)d_in[3];
    const float* ee  = (const float*)d_in[4];
    const float* Wl0 = (const float*)d_in[5];
    const float* bl0 = (const float*)d_in[6];
    const float* Wr0 = (const float*)d_in[7];
    const float* Wl1 = (const float*)d_in[8];
    const float* bl1 = (const float*)d_in[9];
    const float* Wr1 = (const float*)d_in[10];
    const float* Wl2 = (const float*)d_in[11];
    const float* bl2 = (const float*)d_in[12];
    const float* Wr2 = (const float*)d_in[13];
    const float* Wsk0= (const float*)d_in[14];
    const float* Wsk1= (const float*)d_in[15];
    const float* g0  = (const float*)d_in[16];
    const float* b0  = (const float*)d_in[17];
    const float* g1  = (const float*)d_in[18];
    const float* b1  = (const float*)d_in[19];
    const float* g2  = (const float*)d_in[20];
    const float* b2  = (const float*)d_in[21];
    const float* a0  = (const float*)d_in[22];
    const float* a1  = (const float*)d_in[23];
    const float* a2  = (const float*)d_in[24];

    float* h    = symaddr(g_h);
    float* h1   = symaddr(g_h1);
    float* h2   = symaddr(g_h2);
    float* skp  = symaddr(g_skip);
    float* agg  = symaddr(g_agg);
    float* pre  = symaddr(g_pre);
    float* out  = (float*)d_out;

    cudaFuncSetAttribute(k_mma, cudaFuncAttributeMaxDynamicSharedMemorySize, SM_BYTES);

    dim3 mg(NN/128, HH/128);   // (512, 2)

    // --- graph preprocessing ---
    k_zero   <<<NN/256, 256>>>();
    k_hist   <<<NE/256, 256>>>(row, col, ea);
    k_scanA  <<<256, 256>>>();
    k_scanB  <<<1, 256>>>();
    k_scanC  <<<NN/256, 256>>>();
    k_scatter<<<NE/256, 256>>>(row, col);
    k_inith  <<<NN, 64>>>(x, en, ee);

    // --- layer 0 ---
    k_agg    <<<NN/8, 256>>>(h, agg);
    k_mma    <<<mg, 256, SM_BYTES>>>(agg, Wl0, h, Wr0, bl0, nullptr, nullptr, pre, 1);
    k_bnstats<<<256, 256>>>();
    k_bnfinal<<<1, 256>>>(g0, b0);
    k_bnact  <<<NN*H4/256, 256>>>(a0, h1);

    // --- layer 1 ---
    k_mma    <<<mg, 256, SM_BYTES>>>(h, Wsk0, nullptr, nullptr, nullptr, h1, nullptr, skp, 0);
    k_agg    <<<NN/8, 256>>>(skp, agg);
    k_mma    <<<mg, 256, SM_BYTES>>>(agg, Wl1, skp, Wr1, bl1, nullptr, nullptr, pre, 1);
    k_bnstats<<<256, 256>>>();
    k_bnfinal<<<1, 256>>>(g1, b1);
    k_bnact  <<<NN*H4/256, 256>>>(a1, h2);

    // --- layer 2 ---
    k_mma    <<<mg, 256, SM_BYTES>>>(h, Wsk1, nullptr, nullptr, nullptr, h1, h2, skp, 0);
    k_agg    <<<NN/8, 256>>>(skp, agg);
    k_mma    <<<mg, 256, SM_BYTES>>>(agg, Wl2, skp, Wr2, bl2, nullptr, nullptr, pre, 1);
    k_bnstats<<<256, 256>>>();
    k_bnfinal<<<1, 256>>>(g2, b2);
    k_bnact  <<<NN*H4/256, 256>>>(a2, out);
}